// round 13
// baseline (speedup 1.0000x reference)
#include <cuda_runtime.h>
#include <cuda_bf16.h>
#include <cstdint>
#include <math.h>

// Problem constants
#define SIZE_U   6000
#define SIZE_V   6000
#define N_TOTAL  12000
#define DIM      256
#define KTOP     20
#define ROW_LEN  12000
#define CAP      1024

#define OUT_X    0ull
#define OUT_US   36000000ull
#define OUT_VS   37536000ull

// bf16 split scratch: row n in [0,12000) = concat(u_s, v_s), col in [0,256)
__device__ __nv_bfloat16 g_hi[(size_t)N_TOTAL * DIM];
__device__ __nv_bfloat16 g_lo[(size_t)N_TOTAL * DIM];

// ---------------------------------------------------------------------------
// Mask dtype detection (packed bool vs 32-bit word per element).
// ---------------------------------------------------------------------------
__device__ int g_mask_is_bool;

__global__ void detect_mask_kernel(const unsigned* __restrict__ m) {
    __shared__ int s_word, s_bool;
    if (threadIdx.x == 0) { s_word = 0; s_bool = 0; }
    __syncthreads();
    for (int i = threadIdx.x; i < 3000; i += blockDim.x) {
        unsigned w = m[i];
        if (w & 0xFEFEFEFEu)        atomicOr(&s_word, 1);
        else if (w & 0xFFFFFF00u)   atomicOr(&s_bool, 1);
    }
    __syncthreads();
    if (threadIdx.x == 0) g_mask_is_bool = (s_bool && !s_word) ? 1 : 0;
}

// ---------------------------------------------------------------------------
// Kernel 1: per-row top-20, weighted merge, mask select, bf16 hi/lo emit.
// Fast path: single-pass rank selection over ~84 threshold candidates.
// ---------------------------------------------------------------------------
__global__ __launch_bounds__(256)
void topk_merge_kernel(const float* __restrict__ u, const float* __restrict__ v,
                       const float* __restrict__ sim, const void* __restrict__ mask,
                       float* __restrict__ out)
{
    const int n   = blockIdx.x;
    const int tid = threadIdx.x;

    bool keep;
    if (g_mask_is_bool) keep = ((const unsigned char*)mask)[n] != 0;
    else                keep = ((const unsigned*)mask)[n]      != 0;

    const float* feat = (n < SIZE_U) ? (u + (size_t)n * DIM)
                                     : (v + (size_t)(n - SIZE_U) * DIM);
    float* dst = (n < SIZE_U) ? (out + OUT_US + (size_t)n * DIM)
                              : (out + OUT_VS + (size_t)(n - SIZE_U) * DIM);

    if (keep) {
        float x = feat[tid];
        dst[tid] = x;
        __nv_bfloat16 h = __float2bfloat16(x);
        g_hi[(size_t)n * DIM + tid] = h;
        g_lo[(size_t)n * DIM + tid] = __float2bfloat16(x - __bfloat162float(h));
        return;
    }

    __shared__ float s_cval[CAP];
    __shared__ int   s_cidx[CAP];
    __shared__ int   s_cnt;
    __shared__ float s_rval[256];
    __shared__ int   s_ridx[256];
    __shared__ float s_selv[KTOP];
    __shared__ int   s_seli[KTOP];
    __shared__ float s_wsum;

    const float T0 = 0.993f;
    const float4* row4 = (const float4*)(sim + (size_t)n * ROW_LEN);

    if (tid == 0) s_cnt = 0;
    __syncthreads();

    for (int i = tid; i < ROW_LEN / 4; i += 256) {
        float4 sv = row4[i];
        if (sv.x > T0) { int p = atomicAdd(&s_cnt, 1); if (p < CAP) { s_cval[p] = sv.x; s_cidx[p] = 4*i;   } }
        if (sv.y > T0) { int p = atomicAdd(&s_cnt, 1); if (p < CAP) { s_cval[p] = sv.y; s_cidx[p] = 4*i+1; } }
        if (sv.z > T0) { int p = atomicAdd(&s_cnt, 1); if (p < CAP) { s_cval[p] = sv.z; s_cidx[p] = 4*i+2; } }
        if (sv.w > T0) { int p = atomicAdd(&s_cnt, 1); if (p < CAP) { s_cval[p] = sv.w; s_cidx[p] = 4*i+3; } }
    }
    __syncthreads();
    const int cnt = s_cnt;

    if (cnt >= KTOP && cnt <= CAP) {
        float myv[4]; int myi[4]; int myrank[4];
        int nown = 0;
        #pragma unroll
        for (int q = 0; q < 4; q++) {
            int c = tid + q * 256;
            if (c < cnt) { myv[q] = s_cval[c]; myi[q] = s_cidx[c]; myrank[q] = 0; nown = q + 1; }
        }
        if (nown > 0) {
            for (int j = 0; j < cnt; j++) {
                float vj = s_cval[j]; int ij = s_cidx[j];
                #pragma unroll
                for (int q = 0; q < 4; q++) {
                    if (q < nown &&
                        (vj > myv[q] || (vj == myv[q] && ij < myi[q]))) myrank[q]++;
                }
            }
            #pragma unroll
            for (int q = 0; q < 4; q++) {
                if (q < nown && myrank[q] < KTOP) {
                    s_selv[myrank[q]] = myv[q];
                    s_seli[myrank[q]] = myi[q];
                }
            }
        }
        __syncthreads();
    } else {
        const float* row = sim + (size_t)n * ROW_LEN;
        for (int j = 0; j < KTOP; j++) {
            float bv = -3e38f; int bi = 0x7fffffff;
            for (int i = tid; i < ROW_LEN; i += 256) {
                float vv = row[i];
                bool used = false;
                for (int q = 0; q < j; q++) if (s_seli[q] == i) used = true;
                if (!used && (vv > bv || (vv == bv && i < bi))) { bv = vv; bi = i; }
            }
            s_rval[tid] = bv; s_ridx[tid] = bi;
            __syncthreads();
            for (int s = 128; s; s >>= 1) {
                if (tid < s) {
                    float v2 = s_rval[tid + s]; int i2 = s_ridx[tid + s];
                    if (v2 > s_rval[tid] || (v2 == s_rval[tid] && i2 < s_ridx[tid])) {
                        s_rval[tid] = v2; s_ridx[tid] = i2;
                    }
                }
                __syncthreads();
            }
            if (tid == 0) { s_selv[j] = s_rval[0]; s_seli[j] = s_ridx[0]; }
            __syncthreads();
        }
    }

    if (tid == 0) {
        float s = 0.f;
        #pragma unroll
        for (int q = 0; q < KTOP; q++) s += s_selv[q];
        s_wsum = s;
    }
    __syncthreads();

    float acc = 0.f;
    #pragma unroll
    for (int q = 0; q < KTOP; q++) {
        int id = s_seli[q];
        const float* f = (id < SIZE_U) ? (u + (size_t)id * DIM)
                                       : (v + (size_t)(id - SIZE_U) * DIM);
        acc += s_selv[q] * f[tid];
    }
    float x = acc / s_wsum;
    dst[tid] = x;
    __nv_bfloat16 h = __float2bfloat16(x);
    g_hi[(size_t)n * DIM + tid] = h;
    g_lo[(size_t)n * DIM + tid] = __float2bfloat16(x - __bfloat162float(h));
}

// ---------------------------------------------------------------------------
// Kernel 2: C = sigmoid(A @ B^T) via bf16 split-fp32 mma.sync, cp.async
// double-buffered. D = Ahi*Bhi + Ahi*Blo + Alo*Bhi, fp32 accumulate.
// CTA tile: 128x256, BK=32. 8 warps in 2x4 grid, each warp 64x64.
// Dynamic smem: 2 stages x (Ah,Al: 128x40 | Bh,Bl: 256x40) bf16.
// ---------------------------------------------------------------------------
#define M6    6000
#define GBM   128
#define GBN   256
#define GBK   32
#define NCH   (DIM / GBK)          // 8
#define LDT   40                   // padded smem row stride (bf16)
#define ARRA  (GBM * LDT * 2)      // 10240 B per A array
#define ARRB2 (GBN * LDT * 2)      // 20480 B per B array
#define STGB  (2 * ARRA + 2 * ARRB2)   // 61440 B per stage
#define SMEM_GEMM (2 * STGB)           // 122880 B

__device__ __forceinline__ unsigned ssa(const void* p) {
    return (unsigned)__cvta_generic_to_shared(p);
}
__device__ __forceinline__ void cp16(unsigned dst, const void* src, int bytes) {
    asm volatile("cp.async.cg.shared.global [%0], [%1], 16, %2;"
                 :: "r"(dst), "l"(src), "r"(bytes));
}
__device__ __forceinline__ void cp_commit() {
    asm volatile("cp.async.commit_group;" ::: "memory");
}
template <int N>
__device__ __forceinline__ void cp_wait() {
    asm volatile("cp.async.wait_group %0;" :: "n"(N) : "memory");
}
__device__ __forceinline__ void ldsm4(unsigned addr, unsigned& d0, unsigned& d1,
                                      unsigned& d2, unsigned& d3) {
    asm volatile("ldmatrix.sync.aligned.m8n8.x4.shared.b16 {%0,%1,%2,%3}, [%4];"
                 : "=r"(d0), "=r"(d1), "=r"(d2), "=r"(d3) : "r"(addr));
}
__device__ __forceinline__ void mma16816(float* c, const unsigned* a, unsigned b0, unsigned b1) {
    asm volatile(
        "mma.sync.aligned.m16n8k16.row.col.f32.bf16.bf16.f32 "
        "{%0,%1,%2,%3}, {%4,%5,%6,%7}, {%8,%9}, {%0,%1,%2,%3};"
        : "+f"(c[0]), "+f"(c[1]), "+f"(c[2]), "+f"(c[3])
        : "r"(a[0]), "r"(a[1]), "r"(a[2]), "r"(a[3]), "r"(b0), "r"(b1));
}

__global__ __launch_bounds__(256, 1)
void gemm_sigmoid_mma_kernel(float* __restrict__ C)
{
    extern __shared__ char smem[];
    const unsigned sb = ssa(smem);

    const int tid  = threadIdx.x;
    const int lane = tid & 31;
    const int wid  = tid >> 5;
    const int wr   = (wid >> 2) * 64;   // warp row offset: 0 / 64
    const int wc   = (wid & 3) * 64;    // warp col offset: 0/64/128/192
    const int row0 = blockIdx.y * GBM;
    const int col0 = blockIdx.x * GBN;

    float acc[4][8][4];
    #pragma unroll
    for (int i = 0; i < 4; i++)
        #pragma unroll
        for (int j = 0; j < 8; j++)
            #pragma unroll
            for (int q = 0; q < 4; q++) acc[i][j][q] = 0.f;

    // Stage layout: [Ah | Al | Bh | Bl], rows x 32 cols, 16B chunks.
    auto load_stage = [&](int st, int kc) {
        const unsigned stbase = sb + st * STGB;
        // A arrays: 128 rows x 4 chunks = 512, 2 per thread
        #pragma unroll
        for (int arr = 0; arr < 2; arr++) {
            const __nv_bfloat16* gsrc = arr ? g_lo : g_hi;
            const int rlim = M6 - row0;
            #pragma unroll
            for (int it = 0; it < 2; it++) {
                int idx = it * 256 + tid;
                int row = idx >> 2;
                int c4  = idx & 3;
                const void* src = gsrc + (size_t)(row0 + row) * DIM + kc + c4 * 8;
                unsigned dst = stbase + arr * ARRA + row * (LDT * 2) + c4 * 16;
                cp16(dst, src, (row < rlim) ? 16 : 0);
            }
        }
        // B arrays: 256 rows x 4 chunks = 1024, 4 per thread
        #pragma unroll
        for (int arr = 0; arr < 2; arr++) {
            const __nv_bfloat16* gsrc = arr ? g_lo : g_hi;
            const int rlim = M6 - col0;
            #pragma unroll
            for (int it = 0; it < 4; it++) {
                int idx = it * 256 + tid;
                int row = idx >> 2;
                int c4  = idx & 3;
                const void* src = gsrc + (size_t)(SIZE_U + col0 + row) * DIM + kc + c4 * 8;
                unsigned dst = stbase + 2 * ARRA + arr * ARRB2 + row * (LDT * 2) + c4 * 16;
                cp16(dst, src, (row < rlim) ? 16 : 0);
            }
        }
        cp_commit();
    };

    load_stage(0, 0);

    for (int c = 0; c < NCH; c++) {
        const int st = c & 1;
        if (c + 1 < NCH) load_stage(st ^ 1, (c + 1) * GBK);
        if (c + 1 < NCH) cp_wait<1>(); else cp_wait<0>();
        __syncthreads();

        const __nv_bfloat16* sAh = (const __nv_bfloat16*)(smem + st * STGB);
        const __nv_bfloat16* sAl = (const __nv_bfloat16*)(smem + st * STGB + ARRA);
        const __nv_bfloat16* sBh = (const __nv_bfloat16*)(smem + st * STGB + 2 * ARRA);
        const __nv_bfloat16* sBl = (const __nv_bfloat16*)(smem + st * STGB + 2 * ARRA + ARRB2);

        #pragma unroll
        for (int ks = 0; ks < 2; ks++) {
            const int kb = ks * 16;
            unsigned ah[4][4], al[4][4];
            {
                const int arow = (lane & 15);
                const int acol = kb + ((lane & 16) >> 1);
                #pragma unroll
                for (int mf = 0; mf < 4; mf++) {
                    int r = wr + mf * 16 + arow;
                    ldsm4(ssa(sAh + r * LDT + acol), ah[mf][0], ah[mf][1], ah[mf][2], ah[mf][3]);
                    ldsm4(ssa(sAl + r * LDT + acol), al[mf][0], al[mf][1], al[mf][2], al[mf][3]);
                }
            }
            unsigned bh[4][4], bl[4][4];
            {
                const int brow = (lane & 7) + ((lane & 16) >> 1);
                const int bcol = kb + (lane & 8);
                #pragma unroll
                for (int nf2 = 0; nf2 < 4; nf2++) {
                    int r = wc + nf2 * 16 + brow;
                    ldsm4(ssa(sBh + r * LDT + bcol), bh[nf2][0], bh[nf2][1], bh[nf2][2], bh[nf2][3]);
                    ldsm4(ssa(sBl + r * LDT + bcol), bl[nf2][0], bl[nf2][1], bl[nf2][2], bl[nf2][3]);
                }
            }
            #pragma unroll
            for (int mf = 0; mf < 4; mf++)
                #pragma unroll
                for (int nf = 0; nf < 8; nf++) {
                    const int n2 = nf >> 1, h = (nf & 1) * 2;
                    mma16816(acc[mf][nf], ah[mf], bh[n2][h], bh[n2][h + 1]);
                    mma16816(acc[mf][nf], ah[mf], bl[n2][h], bl[n2][h + 1]);
                    mma16816(acc[mf][nf], al[mf], bh[n2][h], bh[n2][h + 1]);
                }
        }
        __syncthreads();   // stage st fully consumed before reload
    }

    // Epilogue: sigmoid + store.
    const int g = lane >> 2, t = lane & 3;
    #pragma unroll
    for (int mf = 0; mf < 4; mf++) {
        int r0 = row0 + wr + mf * 16 + g;
        #pragma unroll
        for (int nf = 0; nf < 8; nf++) {
            int c = col0 + wc + nf * 8 + t * 2;
            if (c >= M6) continue;
            if (r0 < M6) {
                float2 o;
                o.x = __fdividef(1.f, 1.f + __expf(-acc[mf][nf][0]));
                o.y = __fdividef(1.f, 1.f + __expf(-acc[mf][nf][1]));
                *(float2*)(C + (size_t)r0 * M6 + c) = o;
            }
            int r1 = r0 + 8;
            if (r1 < M6) {
                float2 o;
                o.x = __fdividef(1.f, 1.f + __expf(-acc[mf][nf][2]));
                o.y = __fdividef(1.f, 1.f + __expf(-acc[mf][nf][3]));
                *(float2*)(C + (size_t)r1 * M6 + c) = o;
            }
        }
    }
}

// ---------------------------------------------------------------------------
extern "C" void kernel_launch(void* const* d_in, const int* in_sizes, int n_in,
                              void* d_out, int out_size)
{
    const float* u   = (const float*)d_in[0];
    const float* v   = (const float*)d_in[1];
    const float* sim = (const float*)d_in[2];
    const void*  msk = d_in[3];
    float* out = (float*)d_out;

    detect_mask_kernel<<<1, 256>>>((const unsigned*)msk);
    topk_merge_kernel<<<N_TOTAL, 256>>>(u, v, sim, msk, out);

    cudaFuncSetAttribute(gemm_sigmoid_mma_kernel,
                         cudaFuncAttributeMaxDynamicSharedMemorySize, SMEM_GEMM);
    dim3 g((M6 + GBN - 1) / GBN, (M6 + GBM - 1) / GBM);
    gemm_sigmoid_mma_kernel<<<g, 256, SMEM_GEMM>>>(out + OUT_X);
}